// round 5
// baseline (speedup 1.0000x reference)
#include <cuda_runtime.h>
#include <cuda_bf16.h>
#include <cstdint>

// Problem constants (B=32, T=2048, D_IN=1024, H1=512, H2=32)
#define NB_   32
#define T_    2048
#define DIN   1024
#define H1_   512
#define ROWS  (NB_ * T_)   // 65536

// GEMM tiling
#define MB    128          // rows per block
#define NBLK  256          // h1-cols per block (512 split into 2 N-blocks)
#define KC    32           // k-chunk per smem stage
#define NSTG  (DIN / KC)   // 32 stages

#define AS_STRIDE 40       // 80B row stride: 80*r mod 128 distinct for 8 rows -> LDSM conflict-free
#define BS_STRIDE 264      // 528B row stride: 16B-aligned, 528 mod 128 = 16 -> conflict-free

// ---------------- device scratch (static: no allocations allowed) ----------------
__device__ __nv_bfloat16 g_w1b[DIN * H1_];   // W1 in bf16, row-major [k][n]
__device__ float         g_weff[H1_];        // W2 @ W3
__device__ float         g_beff;             // b2 . W3 + b3
__device__ float         g_zpart[2][ROWS];   // per-N-half partial pre-sigmoid logits

// ---------------- kernel 0: prep (re-run every launch; pure function of inputs) ----
__global__ void prep_kernel(const float* __restrict__ W1,
                            const float* __restrict__ W2,
                            const float* __restrict__ b2,
                            const float* __restrict__ W3,
                            const float* __restrict__ b3) {
    int gid    = blockIdx.x * blockDim.x + threadIdx.x;
    int stride = gridDim.x * blockDim.x;
    for (int i = gid; i < DIN * H1_; i += stride)
        g_w1b[i] = __float2bfloat16(W1[i]);
    if (gid < H1_) {
        float s = 0.f;
        #pragma unroll
        for (int c = 0; c < 32; ++c) s += W2[gid * 32 + c] * W3[c];
        g_weff[gid] = s;
    }
    if (gid == 0) {
        float s = b3[0];
        #pragma unroll
        for (int c = 0; c < 32; ++c) s += b2[c] * W3[c];
        g_beff = s;
    }
}

// ---------------- kernel 1: fused GEMM + bias + relu + weff-dot ----------------
struct __align__(16) Smem {
    __nv_bfloat16 As[2][MB][AS_STRIDE];   // 20480 B
    __nv_bfloat16 Bs[2][KC][BS_STRIDE];   // 33792 B
    float b1s[NBLK];                      //  1024 B
    float wsm[NBLK];                      //  1024 B
    float zs[MB];                         //   512 B
};                                        // total 56832 B (dynamic smem)

__global__ __launch_bounds__(256, 1)
void mlp_gemm_kernel(const float* __restrict__ A, const float* __restrict__ b1) {
    extern __shared__ char smem_raw[];
    Smem& sm = *reinterpret_cast<Smem*>(smem_raw);

    const int tid  = threadIdx.x;
    const int lane = tid & 31;
    const int warp = tid >> 5;
    const int wm   = warp >> 1;   // 0..3  (M groups of 32 rows)
    const int wn   = warp & 1;    // 0..1  (N groups of 128 cols)

    const int nt_blk   = blockIdx.x & 1;     // which 256-col half of H1
    const int row_tile = blockIdx.x >> 1;    // 0..511
    const int row_base = row_tile * MB;
    const int n_base   = nt_blk * NBLK;

    // epilogue constants + zero row sums (covered by the prologue __syncthreads)
    sm.b1s[tid] = b1[n_base + tid];
    sm.wsm[tid] = g_weff[n_base + tid];
    if (tid < MB) sm.zs[tid] = 0.f;

    float acc[2][16][4];
    #pragma unroll
    for (int a = 0; a < 2; ++a)
        #pragma unroll
        for (int b = 0; b < 16; ++b)
            #pragma unroll
            for (int c = 0; c < 4; ++c) acc[a][b][c] = 0.f;

    const float*         Ab = A + (size_t)row_base * DIN;
    const __nv_bfloat16* Bb = g_w1b + n_base;

    const uint32_t as_u = (uint32_t)__cvta_generic_to_shared(&sm.As[0][0][0]);
    const uint32_t bs_u = (uint32_t)__cvta_generic_to_shared(&sm.Bs[0][0][0]);
    const uint32_t AS_BUF = MB * AS_STRIDE * 2;
    const uint32_t BS_BUF = KC * BS_STRIDE * 2;

    float4 ar[4];  // A staging registers

    auto loadB = [&](int buf, int s) {   // cp.async bf16 W1 tile: KC x 256
        const int k0 = s * KC;
        #pragma unroll
        for (int i = 0; i < 4; ++i) {
            int lin = tid + i * 256;                 // 0..1023
            int r   = lin >> 5;                      // 0..31
            int c   = lin & 31;                      // 16B chunk
            uint32_t dst = bs_u + buf * BS_BUF + (uint32_t)(r * BS_STRIDE + c * 8) * 2u;
            const void* src = Bb + (size_t)(k0 + r) * H1_ + c * 8;
            asm volatile("cp.async.cg.shared.global [%0], [%1], 16;\n" :: "r"(dst), "l"(src));
        }
    };
    auto loadA = [&](int s) {            // LDG fp32 A tile: MB x KC
        const int k0 = s * KC;
        #pragma unroll
        for (int i = 0; i < 4; ++i) {
            int lin = tid + i * 256;                 // 0..1023
            int r   = lin >> 3;                      // 0..127
            int c4  = lin & 7;                       // float4 within row
            ar[i] = *reinterpret_cast<const float4*>(Ab + (size_t)r * DIN + k0 + c4 * 4);
        }
    };
    auto storeA = [&](int buf) {         // fp32 -> bf16 -> smem
        #pragma unroll
        for (int i = 0; i < 4; ++i) {
            int lin = tid + i * 256;
            int r   = lin >> 3;
            int c4  = lin & 7;
            __nv_bfloat162 p0 = __floats2bfloat162_rn(ar[i].x, ar[i].y);
            __nv_bfloat162 p1 = __floats2bfloat162_rn(ar[i].z, ar[i].w);
            uint32_t u0 = *reinterpret_cast<uint32_t*>(&p0);
            uint32_t u1 = *reinterpret_cast<uint32_t*>(&p1);
            uint32_t dst = as_u + buf * AS_BUF + (uint32_t)(r * AS_STRIDE + c4 * 4) * 2u;
            asm volatile("st.shared.v2.b32 [%0], {%1,%2};" :: "r"(dst), "r"(u0), "r"(u1));
        }
    };
    auto compute = [&](int buf) {
        const uint32_t abase = as_u + buf * AS_BUF;
        const uint32_t bbase = bs_u + buf * BS_BUF;
        const int lr = lane & 15;
        const int lc = lane >> 4;
        #pragma unroll
        for (int ks = 0; ks < KC; ks += 16) {
            uint32_t a_reg[2][4];
            #pragma unroll
            for (int mt = 0; mt < 2; ++mt) {
                uint32_t addr = abase + (uint32_t)((wm * 32 + mt * 16 + lr) * AS_STRIDE + ks + lc * 8) * 2u;
                asm volatile("ldmatrix.sync.aligned.m8n8.x4.shared.b16 {%0,%1,%2,%3}, [%4];"
                             : "=r"(a_reg[mt][0]), "=r"(a_reg[mt][1]),
                               "=r"(a_reg[mt][2]), "=r"(a_reg[mt][3]) : "r"(addr));
            }
            uint32_t b_reg[16][2];
            #pragma unroll
            for (int nb = 0; nb < 8; ++nb) {   // each x4.trans covers k16 x n16
                uint32_t addr = bbase + (uint32_t)((ks + lr) * BS_STRIDE + wn * 128 + nb * 16 + lc * 8) * 2u;
                uint32_t r0, r1, r2, r3;
                asm volatile("ldmatrix.sync.aligned.m8n8.x4.trans.shared.b16 {%0,%1,%2,%3}, [%4];"
                             : "=r"(r0), "=r"(r1), "=r"(r2), "=r"(r3) : "r"(addr));
                b_reg[nb * 2][0] = r0; b_reg[nb * 2][1] = r1;
                b_reg[nb * 2 + 1][0] = r2; b_reg[nb * 2 + 1][1] = r3;
            }
            #pragma unroll
            for (int mt = 0; mt < 2; ++mt)
                #pragma unroll
                for (int nt = 0; nt < 16; ++nt) {
                    asm volatile(
                        "mma.sync.aligned.m16n8k16.row.col.f32.bf16.bf16.f32 "
                        "{%0,%1,%2,%3}, {%4,%5,%6,%7}, {%8,%9}, {%0,%1,%2,%3};"
                        : "+f"(acc[mt][nt][0]), "+f"(acc[mt][nt][1]),
                          "+f"(acc[mt][nt][2]), "+f"(acc[mt][nt][3])
                        : "r"(a_reg[mt][0]), "r"(a_reg[mt][1]),
                          "r"(a_reg[mt][2]), "r"(a_reg[mt][3]),
                          "r"(b_reg[nt][0]), "r"(b_reg[nt][1]));
                }
        }
    };

    // ---- pipelined main loop (double buffer; cp.async for B, reg-staged A) ----
    loadB(0, 0);
    asm volatile("cp.async.commit_group;");
    loadA(0);
    storeA(0);
    asm volatile("cp.async.wait_group 0;");
    __syncthreads();

    for (int s = 0; s < NSTG; ++s) {
        const int buf = s & 1;
        if (s + 1 < NSTG) {
            loadB(buf ^ 1, s + 1);
            asm volatile("cp.async.commit_group;");
            loadA(s + 1);
        }
        compute(buf);
        if (s + 1 < NSTG) {
            storeA(buf ^ 1);
            asm volatile("cp.async.wait_group 0;");
        }
        __syncthreads();
    }

    // ---- epilogue: bias + relu + weighted row-sum (fused layers 2+3) ----
    const int g = lane >> 2, tig = lane & 3;
    #pragma unroll
    for (int mt = 0; mt < 2; ++mt) {
        float sa = 0.f, sb = 0.f;
        #pragma unroll
        for (int nt = 0; nt < 16; ++nt) {
            int c0 = wn * 128 + nt * 8 + tig * 2;
            float w0 = sm.wsm[c0],  w1 = sm.wsm[c0 + 1];
            float q0 = sm.b1s[c0],  q1 = sm.b1s[c0 + 1];
            float h0 = fmaxf(acc[mt][nt][0] + q0, 0.f);
            float h1 = fmaxf(acc[mt][nt][1] + q1, 0.f);
            float h2 = fmaxf(acc[mt][nt][2] + q0, 0.f);
            float h3 = fmaxf(acc[mt][nt][3] + q1, 0.f);
            sa += h0 * w0 + h1 * w1;
            sb += h2 * w0 + h3 * w1;
        }
        sa += __shfl_xor_sync(0xffffffffu, sa, 1);
        sa += __shfl_xor_sync(0xffffffffu, sa, 2);
        sb += __shfl_xor_sync(0xffffffffu, sb, 1);
        sb += __shfl_xor_sync(0xffffffffu, sb, 2);
        if (tig == 0) {
            atomicAdd(&sm.zs[wm * 32 + mt * 16 + g], sa);
            atomicAdd(&sm.zs[wm * 32 + mt * 16 + g + 8], sb);
        }
    }
    __syncthreads();
    if (tid < MB)
        g_zpart[nt_blk][row_base + tid] = sm.zs[tid];
}

// ---------------- kernel 2: per-sample sigmoid + ragged top-k mean ----------------
__global__ void topk_kernel(const int* __restrict__ seq_len, float* __restrict__ out) {
    __shared__ float s[T_];
    __shared__ float red[8];
    const int b   = blockIdx.x;
    const int tid = threadIdx.x;
    const int L   = seq_len[b];
    const float beff = g_beff;

    for (int i = tid; i < T_; i += blockDim.x) {
        float v = -1.0f;  // below sigmoid range -> never in top-k
        if (i < L) {
            float z = g_zpart[0][b * T_ + i] + g_zpart[1][b * T_ + i] + beff;
            v = 1.0f / (1.0f + expf(-z));
        }
        s[i] = v;
    }
    __syncthreads();

    // bitonic sort, descending
    for (int size = 2; size <= T_; size <<= 1) {
        for (int stride = size >> 1; stride > 0; stride >>= 1) {
            for (int i = tid; i < T_; i += blockDim.x) {
                int j = i ^ stride;
                if (j > i) {
                    bool desc = ((i & size) == 0);
                    float x = s[i], y = s[j];
                    if ((x < y) == desc) { s[i] = y; s[j] = x; }
                }
            }
            __syncthreads();
        }
    }

    const int k = L / 16 + 1;   // k <= L always
    float p = 0.f;
    for (int i = tid; i < k; i += blockDim.x) p += s[i];
    p += __shfl_xor_sync(0xffffffffu, p, 16);
    p += __shfl_xor_sync(0xffffffffu, p, 8);
    p += __shfl_xor_sync(0xffffffffu, p, 4);
    p += __shfl_xor_sync(0xffffffffu, p, 2);
    p += __shfl_xor_sync(0xffffffffu, p, 1);
    if ((tid & 31) == 0) red[tid >> 5] = p;
    __syncthreads();
    if (tid == 0) {
        float sum = 0.f;
        #pragma unroll
        for (int w = 0; w < 8; ++w) sum += red[w];
        out[b] = sum / (float)k;
    }
}

// ---------------- entry point ----------------
// Inputs (metadata order = setup_inputs dict order):
//  0: avf_out [32,2048,1024] f32   1: W1 [1024,512] f32   2: b1 [512] f32
//  3: W2 [512,32] f32              4: b2 [32] f32         5: W3 [32,1] f32
//  6: b3 [1] f32                   7: seq_len [32] i32
// Output: [32] f32
extern "C" void kernel_launch(void* const* d_in, const int* in_sizes, int n_in,
                              void* d_out, int out_size) {
    const float* avf = (const float*)d_in[0];
    const float* W1  = (const float*)d_in[1];
    const float* b1  = (const float*)d_in[2];
    const float* W2  = (const float*)d_in[3];
    const float* b2  = (const float*)d_in[4];
    const float* W3  = (const float*)d_in[5];
    const float* b3  = (const float*)d_in[6];
    const int*   seq = (const int*)d_in[7];
    float*       out = (float*)d_out;

    cudaFuncSetAttribute(mlp_gemm_kernel,
                         cudaFuncAttributeMaxDynamicSharedMemorySize,
                         (int)sizeof(Smem));

    prep_kernel<<<256, 256>>>(W1, W2, b2, W3, b3);
    mlp_gemm_kernel<<<(ROWS / MB) * (H1_ / NBLK), 256, sizeof(Smem)>>>(avf, b1);
    topk_kernel<<<NB_, 256>>>(seq, out);
}